// round 1
// baseline (speedup 1.0000x reference)
#include <cuda_runtime.h>
#include <cuda_bf16.h>

#define ROWLEN 8192
#define NROWS  4096
#define K      8
#define THREADS 256

// Order-preserving map: float -> uint32 such that f1 > f2  <=>  u1 > u2.
__device__ __forceinline__ unsigned fflip(float f) {
    unsigned u = __float_as_uint(f);
    return (u & 0x80000000u) ? ~u : (u | 0x80000000u);
}
__device__ __forceinline__ float funflip(unsigned u) {
    return __uint_as_float((u & 0x80000000u) ? (u ^ 0x80000000u) : ~u);
}

__device__ __forceinline__ unsigned long long umax64(unsigned long long a, unsigned long long b) {
    return a > b ? a : b;
}

__global__ __launch_bounds__(THREADS)
void topk8_kernel(const float* __restrict__ x,
                  float* __restrict__ out_vals,
                  float* __restrict__ out_idx) {
    __shared__ unsigned long long sm[THREADS * K];

    const int row = blockIdx.x;
    const int tid = threadIdx.x;
    const float4* __restrict__ p =
        reinterpret_cast<const float4*>(x + (size_t)row * ROWLEN);

    // -------- per-thread top-8 (sorted descending in registers) --------
    unsigned long long top[K];
#pragma unroll
    for (int i = 0; i < K; i++) top[i] = 0ULL;

#pragma unroll
    for (int i = 0; i < ROWLEN / 4 / THREADS; i++) {     // 8 float4 per thread
        const int vi = tid + i * THREADS;
        const float4 v = p[vi];
        const int base = vi * 4;
        float f[4] = {v.x, v.y, v.z, v.w};
#pragma unroll
        for (int j = 0; j < 4; j++) {
            // tie-break: smaller index wins -> store complement of index in low bits
            unsigned long long key =
                ((unsigned long long)fflip(f[j]) << 32) |
                (unsigned)(ROWLEN - 1 - (base + j));
            if (key > top[K - 1]) {                      // rare after warmup
                top[K - 1] = key;
#pragma unroll
                for (int s = K - 1; s > 0; s--) {
                    unsigned long long a = top[s - 1], b = top[s];
                    top[s - 1] = a > b ? a : b;
                    top[s]     = a > b ? b : a;
                }
            }
        }
    }

    // -------- block reduction: tree merge of sorted-8 lists --------
#pragma unroll
    for (int j = 0; j < K; j++) sm[tid * K + j] = top[j];

    for (int stride = THREADS / 2; stride >= 1; stride >>= 1) {
        __syncthreads();
        if (tid < stride) {
            unsigned long long a[K], b[K], m[K];
#pragma unroll
            for (int j = 0; j < K; j++) {
                a[j] = sm[tid * K + j];
                b[j] = sm[(tid + stride) * K + j];
            }
            // bitonic top-k merge: max(a[i], reversed b[i]) holds the top-8
            // multiset and is bitonic; 3 compare-exchange stages sort it desc.
#pragma unroll
            for (int j = 0; j < K; j++) m[j] = umax64(a[j], b[K - 1 - j]);
#pragma unroll
            for (int d = K / 2; d >= 1; d >>= 1) {
#pragma unroll
                for (int j = 0; j < K; j++) {
                    if ((j & d) == 0) {
                        unsigned long long lo = m[j], hi = m[j | d];
                        m[j]     = lo > hi ? lo : hi;
                        m[j | d] = lo > hi ? hi : lo;
                    }
                }
            }
#pragma unroll
            for (int j = 0; j < K; j++) sm[tid * K + j] = m[j];
        }
    }

    __syncthreads();
    if (tid < K) {
        unsigned long long key = sm[tid];
        out_vals[(size_t)row * K + tid] = funflip((unsigned)(key >> 32));
        out_idx [(size_t)row * K + tid] =
            (float)(ROWLEN - 1 - (unsigned)(key & 0xFFFFFFFFu));
    }
}

extern "C" void kernel_launch(void* const* d_in, const int* in_sizes, int n_in,
                              void* d_out, int out_size) {
    const float* x = (const float*)d_in[0];
    float* out_vals = (float*)d_out;
    float* out_idx  = out_vals + (size_t)NROWS * K;   // second output region
    topk8_kernel<<<NROWS, THREADS>>>(x, out_vals, out_idx);
}

// round 2
// speedup vs baseline: 2.9246x; 2.9246x over previous
#include <cuda_runtime.h>

#define ROWLEN 8192
#define NROWS  4096
#define K      8
#define THREADS 256
#define NWARP  (THREADS / 32)
#define NF4    (ROWLEN / 4 / THREADS)   // 8 float4 per thread
#define CAP    512

// Order-preserving map: float -> uint32 (f1 > f2 <=> u1 > u2).
__device__ __forceinline__ unsigned fflip(float f) {
    unsigned u = __float_as_uint(f);
    return (u & 0x80000000u) ? ~u : (u | 0x80000000u);
}
__device__ __forceinline__ float funflip(unsigned u) {
    return __uint_as_float((u & 0x80000000u) ? (u ^ 0x80000000u) : ~u);
}
__device__ __forceinline__ unsigned long long mkkey(float f, int idx) {
    // tie-break: smaller index wins -> complement index in low bits
    return ((unsigned long long)fflip(f) << 32) | (unsigned)(ROWLEN - 1 - idx);
}

// Branchy insert into a register-resident sorted-descending top-8.
__device__ __forceinline__ void insert8(unsigned long long (&t)[K],
                                        unsigned long long key) {
    if (key > t[K - 1]) {
        t[K - 1] = key;
#pragma unroll
        for (int s = K - 1; s > 0; s--) {
            unsigned long long a = t[s - 1], b = t[s];
            t[s - 1] = a > b ? a : b;
            t[s]     = a > b ? b : a;
        }
    }
}

// Bitonic top-8 merge of two sorted-desc 8-lists in smem: dst <- top8(dst, src).
__device__ __forceinline__ void merge8(unsigned long long* dst,
                                       const unsigned long long* src) {
    unsigned long long m[K];
#pragma unroll
    for (int j = 0; j < K; j++) {
        unsigned long long a = dst[j], b = src[K - 1 - j];
        m[j] = a > b ? a : b;           // top-8 multiset, bitonic
    }
#pragma unroll
    for (int d = K / 2; d >= 1; d >>= 1) {
#pragma unroll
        for (int j = 0; j < K; j++) {
            if ((j & d) == 0) {
                unsigned long long lo = m[j], hi = m[j | d];
                m[j]     = lo > hi ? lo : hi;
                m[j | d] = lo > hi ? hi : lo;
            }
        }
    }
#pragma unroll
    for (int j = 0; j < K; j++) dst[j] = m[j];
}

__global__ __launch_bounds__(THREADS)
void topk8_kernel(const float* __restrict__ x,
                  float* __restrict__ out_vals,
                  float* __restrict__ out_idx) {
    __shared__ unsigned long long s_list[THREADS * K];  // 16 KB (fallback-sized)
    __shared__ unsigned long long s_cand[CAP];          // 4 KB
    __shared__ float s_bound[NWARP];
    __shared__ float s_t8;
    __shared__ int   s_count;

    const int row  = blockIdx.x;
    const int tid  = threadIdx.x;
    const int warp = tid >> 5;
    const int lane = tid & 31;
    const float4* __restrict__ p =
        reinterpret_cast<const float4*>(x + (size_t)row * ROWLEN);

    // ---- load 32 elements into registers, compute group maxes ----
    float4 v[NF4];
#pragma unroll
    for (int i = 0; i < NF4; i++) v[i] = p[tid + i * THREADS];

    float m[NF4];
#pragma unroll
    for (int i = 0; i < NF4; i++)
        m[i] = fmaxf(fmaxf(v[i].x, v[i].y), fmaxf(v[i].z, v[i].w));

    float tmax = m[0];
#pragma unroll
    for (int i = 1; i < NF4; i++) tmax = fmaxf(tmax, m[i]);

    // ---- safe threshold: 8th largest of each warp's 32 thread-maxes ----
    // Bitonic sort ascending across lanes; 8th largest lands at lane 24.
    float s = tmax;
#pragma unroll
    for (int k = 2; k <= 32; k <<= 1) {
#pragma unroll
        for (int j = k >> 1; j > 0; j >>= 1) {
            float o = __shfl_xor_sync(0xffffffffu, s, j);
            bool dir_asc = ((lane & k) == 0);
            bool lower   = ((lane & j) == 0);
            s = (dir_asc != lower) ? fmaxf(s, o) : fminf(s, o);
        }
    }
    float wbound = __shfl_sync(0xffffffffu, s, 24);
    if (lane == 0) s_bound[warp] = wbound;
    __syncthreads();

    if (tid == 0) {
        float t8 = s_bound[0];
#pragma unroll
        for (int w = 1; w < NWARP; w++) t8 = fmaxf(t8, s_bound[w]);
        s_t8 = t8;            // t8 <= true 8th-largest of row (subset property)
        s_count = 0;
    }
    __syncthreads();
    const float t8 = s_t8;

    // ---- candidate collection (hot path: 8 compares / 32 elements) ----
#pragma unroll
    for (int i = 0; i < NF4; i++) {
        if (m[i] >= t8) {     // rare
            const int base = (tid + i * THREADS) * 4;
            float f[4] = {v[i].x, v[i].y, v[i].z, v[i].w};
#pragma unroll
            for (int j = 0; j < 4; j++) {
                if (f[j] >= t8) {
                    int pos = atomicAdd(&s_count, 1);
                    if (pos < CAP) s_cand[pos] = mkkey(f[j], base + j);
                }
            }
        }
    }
    __syncthreads();
    const int C = s_count;    // C >= 8 guaranteed

    if (C <= CAP) {
        // ---- warp 0 reduces candidates to 32 sorted-8 lists ----
        if (warp == 0) {
            unsigned long long top[K];
#pragma unroll
            for (int j = 0; j < K; j++) top[j] = 0ULL;
            for (int c = lane; c < C; c += 32) insert8(top, s_cand[c]);
#pragma unroll
            for (int j = 0; j < K; j++) s_list[lane * K + j] = top[j];
        }
        for (int stride = 16; stride >= 1; stride >>= 1) {
            __syncthreads();
            if (tid < stride) merge8(&s_list[tid * K], &s_list[(tid + stride) * K]);
        }
        __syncthreads();
    } else {
        // ---- exact fallback: full per-thread top-8 + 256-way tree merge ----
        unsigned long long top[K];
#pragma unroll
        for (int j = 0; j < K; j++) top[j] = 0ULL;
#pragma unroll
        for (int i = 0; i < NF4; i++) {
            const int base = (tid + i * THREADS) * 4;
            float f[4] = {v[i].x, v[i].y, v[i].z, v[i].w};
#pragma unroll
            for (int j = 0; j < 4; j++) insert8(top, mkkey(f[j], base + j));
        }
#pragma unroll
        for (int j = 0; j < K; j++) s_list[tid * K + j] = top[j];
        for (int stride = THREADS / 2; stride >= 1; stride >>= 1) {
            __syncthreads();
            if (tid < stride) merge8(&s_list[tid * K], &s_list[(tid + stride) * K]);
        }
        __syncthreads();
    }

    if (tid < K) {
        unsigned long long key = s_list[tid];
        out_vals[(size_t)row * K + tid] = funflip((unsigned)(key >> 32));
        out_idx [(size_t)row * K + tid] =
            (float)(ROWLEN - 1 - (unsigned)(key & 0xFFFFFFFFu));
    }
}

extern "C" void kernel_launch(void* const* d_in, const int* in_sizes, int n_in,
                              void* d_out, int out_size) {
    const float* x = (const float*)d_in[0];
    float* out_vals = (float*)d_out;
    float* out_idx  = out_vals + (size_t)NROWS * K;
    topk8_kernel<<<NROWS, THREADS>>>(x, out_vals, out_idx);
}